// round 15
// baseline (speedup 1.0000x reference)
#include <cuda_runtime.h>

// Problem constants
#define BB 4
#define NN 4096
#define DD 1024
#define L  32                 // timesteps per chunk
#define LR 24                 // h_local kept in registers for t < LR
#define LS (L - LR)           // h_local in smem for t >= LR (8)
#define C  (NN / L)           // 128 chunks per chain
#define DT 256                // threads per block = d-tile width
#define NCOL (BB * (DD / DT)) // 16 independent chains
#define NBLK (C * NCOL)       // 2048 blocks (R5/R14-identical protocol)
#define W  16                 // lookback window width
#define BG 4                  // streaming batch depth (8 loads in flight)

// Scratch (static __device__ globals: allowed; no runtime allocation)
__device__ float2 g_agg [NBLK * DT];
__device__ float2 g_incl[NBLK * DT];
__device__ int    g_flags[NBLK];     // 0 = empty, 1 = aggregate ready, 2 = inclusive ready

// Plain L2 poll: no acquire semantics, no atomic serialization, not hoistable.
__device__ __forceinline__ int ld_flag_cg(const int* p) {
    int v;
    asm volatile("ld.global.cg.b32 %0, [%1];" : "=r"(v) : "l"(p) : "memory");
    return v;
}

__global__ __launch_bounds__(DT, 5)
void assoc_scan_kernel(const float* __restrict__ gates,
                       const float* __restrict__ inputs,
                       float* __restrict__ out)
{
    // Per-thread private stores: [t][tid] -> conflict-free (tid-contiguous banks).
    __shared__ float s_pA[L][DT];     // prefix gate products      (32 KB)
    __shared__ float s_hl[LS][DT];    // h_local overflow (t>=LR)  ( 8 KB)
    __shared__ int s_take, s_done;

    const int bx    = blockIdx.x;
    const int chunk = bx >> 4;        // slow-varying -> predecessors scheduled first
    const int col   = bx & 15;        // chain id: (b, d-tile)
    const int tid   = threadIdx.x;

    const int base = ((col >> 2) * NN + chunk * L) * DD + ((col & 3) * DT + tid);

    // ---- Pass 1: stream chunk once (batched loads). h_local -> regs/smem,
    // prefixA -> smem. Inputs are never touched again. ----
    float hl[LR];
    float A = 1.0f, S = 0.0f;
#pragma unroll
    for (int t0 = 0; t0 < L; t0 += BG) {
        float gg[BG], xx[BG];
#pragma unroll
        for (int i = 0; i < BG; i++) {
            gg[i] = __ldg(gates  + base + (t0 + i) * DD);
            xx[i] = __ldg(inputs + base + (t0 + i) * DD);
        }
#pragma unroll
        for (int i = 0; i < BG; i++) {
            const int t = t0 + i;
            S = fmaf(gg[i], S, xx[i]);
            A = A * gg[i];
            if (t < LR) hl[t] = S;
            else        s_hl[t - LR][tid] = S;
            s_pA[t][tid] = A;
        }
    }

    const int slot = bx * DT + tid;
    float accA = 1.0f, accS = 0.0f;   // exclusive prefix (carry) for this chunk

    if (chunk == 0) {
        float2 v; v.x = A; v.y = S;
        __stcg(&g_incl[slot], v);
        __threadfence();
        __syncthreads();
        if (tid == 0) atomicExch(&g_flags[bx], 2);
        // carry = 0: out = h_local directly
#pragma unroll
        for (int t = 0; t < LR; t++)
            out[base + t * DD] = hl[t];
#pragma unroll
        for (int t = LR; t < L; t++)
            out[base + t * DD] = s_hl[t - LR][tid];
        return;
    }

    // Publish aggregate ASAP so successors can make progress.
    {
        float2 v; v.x = A; v.y = S;
        __stcg(&g_agg[slot], v);
        __threadfence();
        __syncthreads();
        if (tid == 0) atomicExch(&g_flags[bx], 1);
    }

    // ---- Windowed decoupled lookback (W=16 ballot window, proven) ----
    int k_hi = chunk - 1;
    for (;;) {
        const int Wc = (k_hi + 1 < W) ? (k_hi + 1) : W;
        if (tid < 32) {
            int take, done;
            const unsigned valid = (1u << Wc) - 1u;
            for (;;) {
                int f = 2;
                if (tid < Wc) f = ld_flag_cg(&g_flags[(k_hi - tid) * 16 + col]);
                unsigned m1 = __ballot_sync(0xffffffffu, f >= 1) & valid;
                unsigned m2 = __ballot_sync(0xffffffffu, f == 2) & valid;
                if (m2) {
                    const int s = __ffs(m2) - 1;           // newest inclusive in window
                    const unsigned need = (1u << s) - 1u;  // newer entries need aggregates
                    if ((m1 & need) == need) { take = s + 1; done = 1; break; }
                }
                if (m1 == valid) { take = Wc; done = 0; break; }
            }
            if (tid == 0) { s_take = take; s_done = done; }
        }
        __syncthreads();
        const int take = s_take;
        const int done = s_done;

        // Fold 'take' predecessors, newest (j=0) to oldest, MLP-4 batches.
        for (int j0 = 0; j0 < take; j0 += 4) {
            const int nb = (take - j0 < 4) ? (take - j0) : 4;
            float2 p0, p1, p2, p3;
            {            const int j = j0;     const float2* s = (done && (j == take-1)) ? g_incl : g_agg;
                         p0 = __ldcg(&s[((k_hi - j) * 16 + col) * DT + tid]); }
            if (nb > 1) { const int j = j0 + 1; const float2* s = (done && (j == take-1)) ? g_incl : g_agg;
                         p1 = __ldcg(&s[((k_hi - j) * 16 + col) * DT + tid]); }
            if (nb > 2) { const int j = j0 + 2; const float2* s = (done && (j == take-1)) ? g_incl : g_agg;
                         p2 = __ldcg(&s[((k_hi - j) * 16 + col) * DT + tid]); }
            if (nb > 3) { const int j = j0 + 3; const float2* s = (done && (j == take-1)) ? g_incl : g_agg;
                         p3 = __ldcg(&s[((k_hi - j) * 16 + col) * DT + tid]); }

            accS = fmaf(accA, p0.y, accS); accA *= p0.x;
            if (nb > 1) { accS = fmaf(accA, p1.y, accS); accA *= p1.x; }
            if (nb > 2) { accS = fmaf(accA, p2.y, accS); accA *= p2.x; }
            if (nb > 3) { accS = fmaf(accA, p3.y, accS); accA *= p3.x; }
        }
        __syncthreads();   // protect s_take/s_done reuse
        if (done) break;
        k_hi -= take;      // chunk 0 always posts inclusive -> guaranteed termination
    }

    // Publish our inclusive prefix: combine(all-predecessors, local)
    {
        float2 inc;
        inc.x = A * accA;
        inc.y = fmaf(A, accS, S);
        __stcg(&g_incl[slot], inc);
        __threadfence();
        __syncthreads();
        if (tid == 0) atomicExch(&g_flags[bx], 2);
    }

    // ---- Emit: out[t] = h_local[t] + carry * prefixA[t]. No global re-read. ----
#pragma unroll
    for (int t = 0; t < LR; t++)
        out[base + t * DD] = fmaf(accS, s_pA[t][tid], hl[t]);
#pragma unroll
    for (int t = LR; t < L; t++)
        out[base + t * DD] = fmaf(accS, s_pA[t][tid], s_hl[t - LR][tid]);
}

extern "C" void kernel_launch(void* const* d_in, const int* in_sizes, int n_in,
                              void* d_out, int out_size)
{
    const float* gates  = (const float*)d_in[0];
    const float* inputs = (const float*)d_in[1];
    float*       out    = (float*)d_out;

    // Ensure the L1/shared carveout admits 5 CTAs x 41KB (idempotent host call,
    // not a graph-captured op, no allocation).
    static int carveout_done = 0;
    if (!carveout_done) {
        cudaFuncSetAttribute(assoc_scan_kernel,
                             cudaFuncAttributePreferredSharedMemoryCarveout,
                             cudaSharedmemCarveoutMaxShared);
        carveout_done = 1;
    }

    void* flags_ptr = nullptr;
    cudaGetSymbolAddress(&flags_ptr, g_flags);
    cudaMemsetAsync(flags_ptr, 0, NBLK * sizeof(int));   // reset chain state (captured node)

    assoc_scan_kernel<<<NBLK, DT>>>(gates, inputs, out);
}

// round 16
// speedup vs baseline: 1.0889x; 1.0889x over previous
#include <cuda_runtime.h>

// Problem constants
#define BB 4
#define NN 4096
#define DD 1024
#define L  32                 // timesteps per chunk
#define C  (NN / L)           // 128 chunks per chain
#define DT 256                // threads per block = d-tile width
#define NCOL (BB * (DD / DT)) // 16 independent chains
#define NBLK (C * NCOL)       // 2048 blocks (R5/R14-identical protocol)
#define W  16                 // lookback window width
#define BG 8                  // streaming batch depth (16 loads in flight, R12-proven)

// Scratch (static __device__ globals: allowed; no runtime allocation)
__device__ float2 g_agg [NBLK * DT];
__device__ float2 g_incl[NBLK * DT];
__device__ int    g_flags[NBLK];     // 0 = empty, 1 = aggregate ready, 2 = inclusive ready

// Plain L2 poll: no acquire semantics, no atomic serialization, not hoistable.
__device__ __forceinline__ int ld_flag_cg(const int* p) {
    int v;
    asm volatile("ld.global.cg.b32 %0, [%1];" : "=r"(v) : "l"(p) : "memory");
    return v;
}

__global__ __launch_bounds__(DT, 4)
void assoc_scan_kernel(const float* __restrict__ gates,
                       const float* __restrict__ inputs,
                       float* __restrict__ out)
{
    // Per-thread private prefix-product store: [t][tid] -> conflict-free.
    __shared__ float s_pA[L][DT];
    __shared__ int s_take, s_done;

    const int bx    = blockIdx.x;
    const int chunk = bx >> 4;        // slow-varying -> predecessors scheduled first
    const int col   = bx & 15;        // chain id: (b, d-tile)
    const int tid   = threadIdx.x;

    const int base = ((col >> 2) * NN + chunk * L) * DD + ((col & 3) * DT + tid);

    // ---- Pass 1: stream chunk once (deep batches -> 16 loads in flight).
    // h_local[t] -> registers, prefixA[t] -> smem. Inputs never touched again. ----
    float hl[L];
    float A = 1.0f, S = 0.0f;
#pragma unroll
    for (int t0 = 0; t0 < L; t0 += BG) {
        float gg[BG], xx[BG];
#pragma unroll
        for (int i = 0; i < BG; i++) {
            gg[i] = __ldg(gates  + base + (t0 + i) * DD);
            xx[i] = __ldg(inputs + base + (t0 + i) * DD);
        }
#pragma unroll
        for (int i = 0; i < BG; i++) {
            S = fmaf(gg[i], S, xx[i]);
            A = A * gg[i];
            hl[t0 + i] = S;
            s_pA[t0 + i][tid] = A;
        }
    }

    const int slot = bx * DT + tid;
    float accA = 1.0f, accS = 0.0f;   // exclusive prefix (carry) for this chunk

    if (chunk == 0) {
        float2 v; v.x = A; v.y = S;
        __stcg(&g_incl[slot], v);
        __threadfence();
        __syncthreads();
        if (tid == 0) atomicExch(&g_flags[bx], 2);
        // carry = 0: out = h_local directly
#pragma unroll
        for (int t = 0; t < L; t++)
            out[base + t * DD] = hl[t];
        return;
    }

    // Publish aggregate ASAP so successors can make progress.
    {
        float2 v; v.x = A; v.y = S;
        __stcg(&g_agg[slot], v);
        __threadfence();
        __syncthreads();
        if (tid == 0) atomicExch(&g_flags[bx], 1);
    }

    // ---- Windowed decoupled lookback (W=16 ballot window, proven) ----
    int k_hi = chunk - 1;
    for (;;) {
        const int Wc = (k_hi + 1 < W) ? (k_hi + 1) : W;
        if (tid < 32) {
            int take, done;
            const unsigned valid = (1u << Wc) - 1u;
            for (;;) {
                int f = 2;
                if (tid < Wc) f = ld_flag_cg(&g_flags[(k_hi - tid) * 16 + col]);
                unsigned m1 = __ballot_sync(0xffffffffu, f >= 1) & valid;
                unsigned m2 = __ballot_sync(0xffffffffu, f == 2) & valid;
                if (m2) {
                    const int s = __ffs(m2) - 1;           // newest inclusive in window
                    const unsigned need = (1u << s) - 1u;  // newer entries need aggregates
                    if ((m1 & need) == need) { take = s + 1; done = 1; break; }
                }
                if (m1 == valid) { take = Wc; done = 0; break; }
            }
            if (tid == 0) { s_take = take; s_done = done; }
        }
        __syncthreads();
        const int take = s_take;
        const int done = s_done;

        // Fold 'take' predecessors, newest (j=0) to oldest, MLP-4 batches.
        for (int j0 = 0; j0 < take; j0 += 4) {
            const int nb = (take - j0 < 4) ? (take - j0) : 4;
            float2 p0, p1, p2, p3;
            {            const int j = j0;     const float2* s = (done && (j == take-1)) ? g_incl : g_agg;
                         p0 = __ldcg(&s[((k_hi - j) * 16 + col) * DT + tid]); }
            if (nb > 1) { const int j = j0 + 1; const float2* s = (done && (j == take-1)) ? g_incl : g_agg;
                         p1 = __ldcg(&s[((k_hi - j) * 16 + col) * DT + tid]); }
            if (nb > 2) { const int j = j0 + 2; const float2* s = (done && (j == take-1)) ? g_incl : g_agg;
                         p2 = __ldcg(&s[((k_hi - j) * 16 + col) * DT + tid]); }
            if (nb > 3) { const int j = j0 + 3; const float2* s = (done && (j == take-1)) ? g_incl : g_agg;
                         p3 = __ldcg(&s[((k_hi - j) * 16 + col) * DT + tid]); }

            accS = fmaf(accA, p0.y, accS); accA *= p0.x;
            if (nb > 1) { accS = fmaf(accA, p1.y, accS); accA *= p1.x; }
            if (nb > 2) { accS = fmaf(accA, p2.y, accS); accA *= p2.x; }
            if (nb > 3) { accS = fmaf(accA, p3.y, accS); accA *= p3.x; }
        }
        __syncthreads();   // protect s_take/s_done reuse
        if (done) break;
        k_hi -= take;      // chunk 0 always posts inclusive -> guaranteed termination
    }

    // Publish our inclusive prefix: combine(all-predecessors, local)
    {
        float2 inc;
        inc.x = A * accA;
        inc.y = fmaf(A, accS, S);
        __stcg(&g_incl[slot], inc);
        __threadfence();
        __syncthreads();
        if (tid == 0) atomicExch(&g_flags[bx], 2);
    }

    // ---- Emit: out[t] = h_local[t] + carry * prefixA[t]. No global re-read. ----
#pragma unroll
    for (int t = 0; t < L; t++)
        out[base + t * DD] = fmaf(accS, s_pA[t][tid], hl[t]);
}

extern "C" void kernel_launch(void* const* d_in, const int* in_sizes, int n_in,
                              void* d_out, int out_size)
{
    const float* gates  = (const float*)d_in[0];
    const float* inputs = (const float*)d_in[1];
    float*       out    = (float*)d_out;

    void* flags_ptr = nullptr;
    cudaGetSymbolAddress(&flags_ptr, g_flags);
    cudaMemsetAsync(flags_ptr, 0, NBLK * sizeof(int));   // reset chain state (captured node)

    assoc_scan_kernel<<<NBLK, DT>>>(gates, inputs, out);
}

// round 17
// speedup vs baseline: 1.1271x; 1.0351x over previous
#include <cuda_runtime.h>

// Problem constants
#define BB 4
#define NN 4096
#define DD 1024
#define L  32                 // timesteps per chunk
#define C  (NN / L)           // 128 chunks per chain
#define DT 256                // threads per block = d-tile width
#define NCOL (BB * (DD / DT)) // 16 independent chains
#define NBLK (C * NCOL)       // 2048 blocks (R14-identical protocol)
#define W  16                 // lookback window width
#define BG 4                  // streaming batch depth (R14 value)

// Scratch (static __device__ globals: allowed; no runtime allocation)
__device__ float2 g_agg [NBLK * DT];
__device__ float2 g_incl[NBLK * DT];
__device__ int    g_flags[NBLK];     // 0 = empty, 1 = aggregate ready, 2 = inclusive ready

// Plain L2 poll: no acquire semantics, no atomic serialization, not hoistable.
__device__ __forceinline__ int ld_flag_cg(const int* p) {
    int v;
    asm volatile("ld.global.cg.b32 %0, [%1];" : "=r"(v) : "l"(p) : "memory");
    return v;
}

__global__ __launch_bounds__(DT, 4)
void assoc_scan_kernel(const float* __restrict__ gates,
                       const float* __restrict__ inputs,
                       float* __restrict__ out)
{
    // Per-thread private prefix-product store: [t][tid] -> conflict-free.
    __shared__ float s_pA[L][DT];
    __shared__ int s_take, s_done;

    const int bx    = blockIdx.x;
    const int chunk = bx >> 4;        // slow-varying -> predecessors scheduled first
    const int col   = bx & 15;        // chain id: (b, d-tile)
    const int tid   = threadIdx.x;

    const int base = ((col >> 2) * NN + chunk * L) * DD + ((col & 3) * DT + tid);

    // ---- Pass 1: stream chunk once (evict-first: zero-reuse data must not
    // displace L2-resident lookback records). h_local -> regs, prefixA -> smem. ----
    float hl[L];
    float A = 1.0f, S = 0.0f;
#pragma unroll
    for (int t0 = 0; t0 < L; t0 += BG) {
        float gg[BG], xx[BG];
#pragma unroll
        for (int i = 0; i < BG; i++) {
            gg[i] = __ldcs(gates  + base + (t0 + i) * DD);
            xx[i] = __ldcs(inputs + base + (t0 + i) * DD);
        }
#pragma unroll
        for (int i = 0; i < BG; i++) {
            S = fmaf(gg[i], S, xx[i]);
            A = A * gg[i];
            hl[t0 + i] = S;
            s_pA[t0 + i][tid] = A;
        }
    }

    const int slot = bx * DT + tid;
    float accA = 1.0f, accS = 0.0f;   // exclusive prefix (carry) for this chunk

    if (chunk == 0) {
        float2 v; v.x = A; v.y = S;
        __stcg(&g_incl[slot], v);
        __threadfence();
        __syncthreads();
        if (tid == 0) atomicExch(&g_flags[bx], 2);
        // carry = 0: out = h_local directly
#pragma unroll
        for (int t = 0; t < L; t++)
            __stcs(out + base + t * DD, hl[t]);
        return;
    }

    // Publish aggregate ASAP so successors can make progress.
    {
        float2 v; v.x = A; v.y = S;
        __stcg(&g_agg[slot], v);
        __threadfence();
        __syncthreads();
        if (tid == 0) atomicExch(&g_flags[bx], 1);
    }

    // ---- Windowed decoupled lookback (W=16 ballot window, proven) ----
    int k_hi = chunk - 1;
    for (;;) {
        const int Wc = (k_hi + 1 < W) ? (k_hi + 1) : W;
        if (tid < 32) {
            int take, done;
            const unsigned valid = (1u << Wc) - 1u;
            for (;;) {
                int f = 2;
                if (tid < Wc) f = ld_flag_cg(&g_flags[(k_hi - tid) * 16 + col]);
                unsigned m1 = __ballot_sync(0xffffffffu, f >= 1) & valid;
                unsigned m2 = __ballot_sync(0xffffffffu, f == 2) & valid;
                if (m2) {
                    const int s = __ffs(m2) - 1;           // newest inclusive in window
                    const unsigned need = (1u << s) - 1u;  // newer entries need aggregates
                    if ((m1 & need) == need) { take = s + 1; done = 1; break; }
                }
                if (m1 == valid) { take = Wc; done = 0; break; }
            }
            if (tid == 0) { s_take = take; s_done = done; }
        }
        __syncthreads();
        const int take = s_take;
        const int done = s_done;

        // Fold 'take' predecessors, newest (j=0) to oldest, MLP-4 batches.
        for (int j0 = 0; j0 < take; j0 += 4) {
            const int nb = (take - j0 < 4) ? (take - j0) : 4;
            float2 p0, p1, p2, p3;
            {            const int j = j0;     const float2* s = (done && (j == take-1)) ? g_incl : g_agg;
                         p0 = __ldcg(&s[((k_hi - j) * 16 + col) * DT + tid]); }
            if (nb > 1) { const int j = j0 + 1; const float2* s = (done && (j == take-1)) ? g_incl : g_agg;
                         p1 = __ldcg(&s[((k_hi - j) * 16 + col) * DT + tid]); }
            if (nb > 2) { const int j = j0 + 2; const float2* s = (done && (j == take-1)) ? g_incl : g_agg;
                         p2 = __ldcg(&s[((k_hi - j) * 16 + col) * DT + tid]); }
            if (nb > 3) { const int j = j0 + 3; const float2* s = (done && (j == take-1)) ? g_incl : g_agg;
                         p3 = __ldcg(&s[((k_hi - j) * 16 + col) * DT + tid]); }

            accS = fmaf(accA, p0.y, accS); accA *= p0.x;
            if (nb > 1) { accS = fmaf(accA, p1.y, accS); accA *= p1.x; }
            if (nb > 2) { accS = fmaf(accA, p2.y, accS); accA *= p2.x; }
            if (nb > 3) { accS = fmaf(accA, p3.y, accS); accA *= p3.x; }
        }
        __syncthreads();   // protect s_take/s_done reuse
        if (done) break;
        k_hi -= take;      // chunk 0 always posts inclusive -> guaranteed termination
    }

    // Publish our inclusive prefix: combine(all-predecessors, local)
    {
        float2 inc;
        inc.x = A * accA;
        inc.y = fmaf(A, accS, S);
        __stcg(&g_incl[slot], inc);
        __threadfence();
        __syncthreads();
        if (tid == 0) atomicExch(&g_flags[bx], 2);
    }

    // ---- Emit: out[t] = h_local[t] + carry * prefixA[t]. Evict-first stores. ----
#pragma unroll
    for (int t = 0; t < L; t++)
        __stcs(out + base + t * DD, fmaf(accS, s_pA[t][tid], hl[t]));
}

extern "C" void kernel_launch(void* const* d_in, const int* in_sizes, int n_in,
                              void* d_out, int out_size)
{
    const float* gates  = (const float*)d_in[0];
    const float* inputs = (const float*)d_in[1];
    float*       out    = (float*)d_out;

    void* flags_ptr = nullptr;
    cudaGetSymbolAddress(&flags_ptr, g_flags);
    cudaMemsetAsync(flags_ptr, 0, NBLK * sizeof(int));   // reset chain state (captured node)

    assoc_scan_kernel<<<NBLK, DT>>>(gates, inputs, out);
}